// round 17
// baseline (speedup 1.0000x reference)
#include <cuda_runtime.h>
#include <cuda_bf16.h>
#include <cstdint>
#include <cstring>

#define CC   256
#define NQKV 768
#define MTOK 65536
#define BWIN 1024
#define NHD  8
#define HDM  32

typedef unsigned long long u64;
typedef unsigned int u32;
typedef __nv_bfloat16 bf16;

// ---------------- scratch ----------------
__device__ float g_qkv[(size_t)MTOK * NQKV];     // window-ordered qkv (fp32)
__device__ bf16 g_a0[(size_t)MTOK * CC];         // x gathered+split hi
__device__ bf16 g_a1[(size_t)MTOK * CC];         // x gathered+split lo
__device__ bf16 g_att0[(size_t)MTOK * CC];       // attn out hi
__device__ bf16 g_att1[(size_t)MTOK * CC];       // attn out lo
__device__ bf16 g_wq0[NQKV * CC];                // W_qkv^T hi [n][k]
__device__ bf16 g_wq1[NQKV * CC];
__device__ bf16 g_wp0[CC * CC];                  // W_proj^T hi
__device__ bf16 g_wp1[CC * CC];

// window-ordered token index -> original token row
__device__ __forceinline__ int src_row(int wt) {
    int bw = wt >> 6, p = wt & 63;
    int b  = bw >> 6, w = bw & 63;
    int wy = w >> 3, wx = w & 7;
    int py = p >> 3, px = p & 7;
    return (b << 12) + ((wy * 8 + py) << 6) + (wx * 8 + px);
}

// ---------------- helpers ----------------
__device__ __forceinline__ u32 cvta_smem(const void* p) {
    u32 a;
    asm("{ .reg .u64 t; cvta.to.shared.u64 t, %1; cvt.u32.u64 %0, t; }" : "=r"(a) : "l"(p));
    return a;
}
__device__ __forceinline__ void cpasync16(u32 saddr, const void* gaddr) {
    asm volatile("cp.async.cg.shared.global [%0], [%1], 16;" :: "r"(saddr), "l"(gaddr));
}
__device__ __forceinline__ void cp_commit() {
    asm volatile("cp.async.commit_group;" ::: "memory");
}
template<int N> __device__ __forceinline__ void cp_wait() {
    asm volatile("cp.async.wait_group %0;" :: "n"(N) : "memory");
}
__device__ __forceinline__ void ldsm4(u32& r0, u32& r1, u32& r2, u32& r3, u32 addr) {
    asm volatile("ldmatrix.sync.aligned.m8n8.x4.shared.b16 {%0,%1,%2,%3}, [%4];"
                 : "=r"(r0), "=r"(r1), "=r"(r2), "=r"(r3) : "r"(addr));
}
__device__ __forceinline__ void mma16816(float* d, const u32* a, const u32* b) {
    asm volatile(
        "mma.sync.aligned.m16n8k16.row.col.f32.bf16.bf16.f32 "
        "{%0,%1,%2,%3}, {%4,%5,%6,%7}, {%8,%9}, {%0,%1,%2,%3};"
        : "+f"(d[0]), "+f"(d[1]), "+f"(d[2]), "+f"(d[3])
        : "r"(a[0]), "r"(a[1]), "r"(a[2]), "r"(a[3]), "r"(b[0]), "r"(b[1]));
}
__device__ __forceinline__ u32 bf2u(__nv_bfloat162 h) {
    u32 v; memcpy(&v, &h, 4); return v;
}

// ---------------------------------------------------------------------------
// split_x: window-gather + hi/lo bf16 split of the input activations
// ---------------------------------------------------------------------------
__global__ void split_x(const float* __restrict__ x) {
    int idx = blockIdx.x * 256 + threadIdx.x;
    int row = idx >> 6, c4 = (idx & 63) * 4;
    float4 v = *(const float4*)(x + (size_t)src_row(row) * CC + c4);
    __nv_bfloat162 h0 = __float22bfloat162_rn(make_float2(v.x, v.y));
    __nv_bfloat162 h1 = __float22bfloat162_rn(make_float2(v.z, v.w));
    float2 g0 = __bfloat1622float2(h0), g1 = __bfloat1622float2(h1);
    __nv_bfloat162 l0 = __float22bfloat162_rn(make_float2(v.x - g0.x, v.y - g0.y));
    __nv_bfloat162 l1 = __float22bfloat162_rn(make_float2(v.z - g1.x, v.w - g1.y));
    *(uint2*)(g_a0 + (size_t)row * CC + c4) = make_uint2(bf2u(h0), bf2u(h1));
    *(uint2*)(g_a1 + (size_t)row * CC + c4) = make_uint2(bf2u(l0), bf2u(l1));
}

// ---------------------------------------------------------------------------
// prep: transpose + hi/lo bf16 split of both weight matrices
// ---------------------------------------------------------------------------
__global__ void prep_w(const float* __restrict__ Wq, const float* __restrict__ Wp) {
    int i = blockIdx.x * 256 + threadIdx.x;
    {
        int n = i >> 8, k = i & 255;
        float f = Wq[k * NQKV + n];
        bf16 h = __float2bfloat16_rn(f);
        g_wq0[i] = h;
        g_wq1[i] = __float2bfloat16_rn(f - __bfloat162float(h));
    }
    if (i < CC * CC) {
        int n = i >> 8, k = i & 255;
        float f = Wp[k * CC + n];
        bf16 h = __float2bfloat16_rn(f);
        g_wp0[i] = h;
        g_wp1[i] = __float2bfloat16_rn(f - __bfloat162float(h));
    }
}

// ---------------------------------------------------------------------------
// HMMA GEMM, all-bf16 operands via cp.async (unchanged from R16)
// ---------------------------------------------------------------------------
template<int NT, bool SCATTER>
__global__ __launch_bounds__(256, 2)
void gemm_cp(const bf16* __restrict__ A0, const bf16* __restrict__ A1,
             const bf16* __restrict__ B0, const bf16* __restrict__ B1,
             const float* __restrict__ bias, float* __restrict__ C)
{
    extern __shared__ __align__(128) char dsm[];
    const u32 sb = cvta_smem(dsm);
    const int tid = threadIdx.x, w = tid >> 5, l = tid & 31;
    const int bn = blockIdx.x, bm = blockIdx.y;

    const int r = tid >> 1, hh = tid & 1;
    const char* pa0 = (const char*)(A0 + (size_t)(bm * 128 + r) * CC) + hh * 32;
    const char* pa1 = (const char*)(A1 + (size_t)(bm * 128 + r) * CC) + hh * 32;
    const char* pb0 = (const char*)(B0 + (size_t)(bn * 128 + r) * CC) + hh * 32;
    const char* pb1 = (const char*)(B1 + (size_t)(bn * 128 + r) * CC) + hh * 32;
    const u32 so = (u32)(r * 80 + hh * 32);

    const int mw = (w & 1) * 64, nw = (w >> 1) * 32;

    float acc[4][2][2][4];
#pragma unroll
    for (int i = 0; i < 4; i++)
#pragma unroll
        for (int jj = 0; jj < 2; jj++)
#pragma unroll
            for (int j = 0; j < 2; j++)
#pragma unroll
                for (int q = 0; q < 4; q++) acc[i][jj][j][q] = 0.f;

    auto issue = [&](int c) {
        u32 stg = sb + (u32)((c & 1) * 40960);
        int kb = c * 64;
        cpasync16(stg + so,              pa0 + kb);
        cpasync16(stg + so + 16,         pa0 + kb + 16);
        cpasync16(stg + 10240 + so,      pa1 + kb);
        cpasync16(stg + 10240 + so + 16, pa1 + kb + 16);
        cpasync16(stg + 20480 + so,      pb0 + kb);
        cpasync16(stg + 20480 + so + 16, pb0 + kb + 16);
        cpasync16(stg + 30720 + so,      pb1 + kb);
        cpasync16(stg + 30720 + so + 16, pb1 + kb + 16);
    };

    auto compute_stage = [&](int s) {
        u32 stg = sb + (u32)(s * 40960);
#pragma unroll
        for (int ks = 0; ks < 2; ks++) {
            u32 ah[4][4], al[4][4], bh[2][4], bl[2][4];
            u32 acol = (u32)(ks * 32 + (l >> 4) * 16);
#pragma unroll
            for (int i = 0; i < 4; i++) {
                u32 arow = (u32)(mw + i * 16 + ((l >> 3) & 1) * 8 + (l & 7));
                ldsm4(ah[i][0], ah[i][1], ah[i][2], ah[i][3], stg + arow * 80 + acol);
                ldsm4(al[i][0], al[i][1], al[i][2], al[i][3], stg + 10240 + arow * 80 + acol);
            }
            u32 bcol = (u32)(ks * 32 + ((l >> 3) & 1) * 16);
#pragma unroll
            for (int jj = 0; jj < 2; jj++) {
                u32 nrow = (u32)(nw + jj * 16 + ((l >> 4) & 1) * 8 + (l & 7));
                ldsm4(bh[jj][0], bh[jj][1], bh[jj][2], bh[jj][3], stg + 20480 + nrow * 80 + bcol);
                ldsm4(bl[jj][0], bl[jj][1], bl[jj][2], bl[jj][3], stg + 30720 + nrow * 80 + bcol);
            }
#pragma unroll
            for (int i = 0; i < 4; i++)
#pragma unroll
                for (int jj = 0; jj < 2; jj++)
#pragma unroll
                    for (int j = 0; j < 2; j++) {
                        float* d = acc[i][jj][j];
                        mma16816(d, ah[i], &bh[jj][j * 2]);
                        mma16816(d, ah[i], &bl[jj][j * 2]);
                        mma16816(d, al[i], &bh[jj][j * 2]);
                    }
        }
    };

    issue(0); cp_commit();
    issue(1); cp_commit();
#pragma unroll
    for (int c = 0; c < 8; c++) {
        if (c < 7) cp_wait<1>(); else cp_wait<0>();
        __syncthreads();
        compute_stage(c & 1);
        if (c < 6) {
            __syncthreads();
            issue(c + 2);
            cp_commit();
        }
    }

    {
        const int g = l >> 2, t = l & 3;
#pragma unroll
        for (int i = 0; i < 4; i++) {
            int gr0 = bm * 128 + mw + i * 16 + g;
            int gr1 = gr0 + 8;
            long row0 = SCATTER ? (long)src_row(gr0) : (long)gr0;
            long row1 = SCATTER ? (long)src_row(gr1) : (long)gr1;
#pragma unroll
            for (int jj = 0; jj < 2; jj++)
#pragma unroll
                for (int j = 0; j < 2; j++) {
                    int gc = bn * 128 + nw + jj * 16 + j * 8 + t * 2;
                    float b0 = bias[gc], b1 = bias[gc + 1];
                    float* d = acc[i][jj][j];
                    *(float2*)(C + (size_t)row0 * NT + gc) = make_float2(d[0] + b0, d[1] + b1);
                    *(float2*)(C + (size_t)row1 * NT + gc) = make_float2(d[2] + b0, d[3] + b1);
                }
        }
    }
}

// ---------------------------------------------------------------------------
// Attention kernel v2: one block per (window, head), 256 threads.
//  - single load phase (Q, K, V, E_k, E_v, banks)
//  - K and V compression run CONCURRENTLY (thread groups 0/1)
//  - softmax: 4 threads/row, shfl reductions, __expf
//  - scores buffer aliases dead staging region; 4 barriers total
// smem layout (floats): q 0..2112 | kf 2112..3696 | vf 3696..5280 |
//   kX 5280..7328 | vX 7328..9376 | ek 9376..11424 | ev 11424..13472
//   sc (64x49=3136) @5280 aliases kX/vX after compression.
// ---------------------------------------------------------------------------
#define ATTN_SMEM (13472 * 4)

__global__ __launch_bounds__(256)
void attn_kernel(const float* __restrict__ Ek, const float* __restrict__ Ev,
                 const float* __restrict__ kbank, const float* __restrict__ vbank)
{
    extern __shared__ float S[];
    float (*q)[33]  = (float(*)[33])(S);
    float (*kf)[33] = (float(*)[33])(S + 2112);
    float (*vf)[33] = (float(*)[33])(S + 3696);
    float* kX = S + 5280;
    float* vX = S + 7328;
    float* ek = S + 9376;
    float* ev = S + 11424;
    float* sc = S + 5280;            // pitch 49, aliases kX/vX

    const int bw  = blockIdx.x >> 3;
    const int h   = blockIdx.x & 7;
    const int tid = threadIdx.x;

    const float* qkvbase = g_qkv + (size_t)(bw * 64) * NQKV + h * HDM;

    // ---- single load phase
    for (int idx = tid; idx < 2048; idx += 256) {
        int p = idx >> 5, d = idx & 31;
        const float* row = qkvbase + p * NQKV;
        q[p][d] = row[d];
        kX[idx] = row[256 + d];
        vX[idx] = row[512 + d];
        ek[idx] = Ek[idx];
        ev[idx] = Ev[idx];
    }
    for (int idx = tid; idx < 512; idx += 256) {
        int g = idx >> 5, d = idx & 31;
        kf[32 + g][d] = kbank[g * CC + h * HDM + d];
        vf[32 + g][d] = vbank[g * CC + h * HDM + d];
    }
    __syncthreads();

    // ---- K and V compression in parallel (group 0: K, group 1: V)
    {
        const int grp = tid >> 7, t = tid & 127;
        const float* E = grp ? ev : ek;
        const float* X = grp ? vX : kX;
        float (*of)[33] = grp ? vf : kf;
        int lk0 = (t >> 3) * 2;
        int d0  = (t & 7) * 4;
        float a00 = 0.f, a01 = 0.f, a02 = 0.f, a03 = 0.f;
        float a10 = 0.f, a11 = 0.f, a12 = 0.f, a13 = 0.f;
#pragma unroll 4
        for (int p = 0; p < 64; p++) {
            float e0 = E[p * 32 + lk0], e1 = E[p * 32 + lk0 + 1];
            float b0 = X[p * 32 + d0 + 0], b1 = X[p * 32 + d0 + 1];
            float b2 = X[p * 32 + d0 + 2], b3 = X[p * 32 + d0 + 3];
            a00 += e0 * b0; a01 += e0 * b1; a02 += e0 * b2; a03 += e0 * b3;
            a10 += e1 * b0; a11 += e1 * b1; a12 += e1 * b2; a13 += e1 * b3;
        }
        of[lk0][d0] = a00; of[lk0][d0 + 1] = a01; of[lk0][d0 + 2] = a02; of[lk0][d0 + 3] = a03;
        of[lk0 + 1][d0] = a10; of[lk0 + 1][d0 + 1] = a11; of[lk0 + 1][d0 + 2] = a12; of[lk0 + 1][d0 + 3] = a13;
    }
    __syncthreads();

    // ---- scores [64][48]: 2 rows x 6 cols per thread (writes alias staging)
    {
        int row0 = (tid & 31) * 2;
        int c0   = (tid >> 5) * 6;
        float acc[2][6];
#pragma unroll
        for (int i = 0; i < 2; i++)
#pragma unroll
            for (int j = 0; j < 6; j++) acc[i][j] = 0.f;
#pragma unroll 4
        for (int d = 0; d < 32; d++) {
            float a0 = q[row0][d], a1 = q[row0 + 1][d];
            float b[6];
#pragma unroll
            for (int j = 0; j < 6; j++) b[j] = kf[c0 + j][d];
#pragma unroll
            for (int j = 0; j < 6; j++) { acc[0][j] += a0 * b[j]; acc[1][j] += a1 * b[j]; }
        }
        const float scale = 0.17677669529663687f;
#pragma unroll
        for (int i = 0; i < 2; i++)
#pragma unroll
            for (int j = 0; j < 6; j++)
                sc[(row0 + i) * 49 + c0 + j] = acc[i][j] * scale;
    }
    __syncthreads();

    // ---- softmax: 4 threads per row, 12 cols each, shfl reductions
    {
        int row = tid >> 2, sub = tid & 3;
        float* r = sc + row * 49 + sub * 12;
        float m = -1e30f;
#pragma unroll
        for (int j = 0; j < 12; j++) m = fmaxf(m, r[j]);
        m = fmaxf(m, __shfl_xor_sync(0xffffffffu, m, 1));
        m = fmaxf(m, __shfl_xor_sync(0xffffffffu, m, 2));
        float s = 0.f;
        float e[12];
#pragma unroll
        for (int j = 0; j < 12; j++) { e[j] = __expf(r[j] - m); s += e[j]; }
        s += __shfl_xor_sync(0xffffffffu, s, 1);
        s += __shfl_xor_sync(0xffffffffu, s, 2);
        float inv = 1.f / s;
#pragma unroll
        for (int j = 0; j < 12; j++) r[j] = e[j] * inv;
    }
    __syncthreads();

    // ---- out[64][32] = P @ V_full: 2 rows x 4 cols per thread; bf16 hi/lo
    {
        int row0 = (tid & 31) * 2;
        int c0   = (tid >> 5) * 4;
        float acc[2][4];
#pragma unroll
        for (int i = 0; i < 2; i++)
#pragma unroll
            for (int j = 0; j < 4; j++) acc[i][j] = 0.f;
#pragma unroll 4
        for (int j = 0; j < 48; j++) {
            float a0 = sc[row0 * 49 + j], a1 = sc[(row0 + 1) * 49 + j];
            float b0 = vf[j][c0 + 0], b1 = vf[j][c0 + 1];
            float b2 = vf[j][c0 + 2], b3 = vf[j][c0 + 3];
            acc[0][0] += a0 * b0; acc[0][1] += a0 * b1; acc[0][2] += a0 * b2; acc[0][3] += a0 * b3;
            acc[1][0] += a1 * b0; acc[1][1] += a1 * b1; acc[1][2] += a1 * b2; acc[1][3] += a1 * b3;
        }
        bf16* o0 = g_att0 + (size_t)(bw * 64) * CC + h * HDM + c0;
        bf16* o1 = g_att1 + (size_t)(bw * 64) * CC + h * HDM + c0;
#pragma unroll
        for (int i = 0; i < 2; i++) {
            __nv_bfloat162 h01 = __float22bfloat162_rn(make_float2(acc[i][0], acc[i][1]));
            __nv_bfloat162 h23 = __float22bfloat162_rn(make_float2(acc[i][2], acc[i][3]));
            float2 g01 = __bfloat1622float2(h01), g23 = __bfloat1622float2(h23);
            __nv_bfloat162 l01 = __float22bfloat162_rn(make_float2(acc[i][0] - g01.x, acc[i][1] - g01.y));
            __nv_bfloat162 l23 = __float22bfloat162_rn(make_float2(acc[i][2] - g23.x, acc[i][3] - g23.y));
            *(uint2*)(o0 + (row0 + i) * CC) = make_uint2(bf2u(h01), bf2u(h23));
            *(uint2*)(o1 + (row0 + i) * CC) = make_uint2(bf2u(l01), bf2u(l23));
        }
    }
}

// ---------------------------------------------------------------------------
extern "C" void kernel_launch(void* const* d_in, const int* in_sizes, int n_in,
                              void* d_out, int out_size)
{
    const float* x      = (const float*)d_in[0];
    const float* W_qkv  = (const float*)d_in[1];
    const float* b_qkv  = (const float*)d_in[2];
    const float* E_k    = (const float*)d_in[3];
    const float* E_v    = (const float*)d_in[4];
    const float* k_bank = (const float*)d_in[5];
    const float* v_bank = (const float*)d_in[6];
    const float* W_proj = (const float*)d_in[7];
    const float* b_proj = (const float*)d_in[8];
    float* out = (float*)d_out;

    float* qkv = nullptr;
    bf16 *a0, *a1, *at0, *at1, *wq0, *wq1, *wp0, *wp1;
    cudaGetSymbolAddress((void**)&qkv, g_qkv);
    cudaGetSymbolAddress((void**)&a0,  g_a0);
    cudaGetSymbolAddress((void**)&a1,  g_a1);
    cudaGetSymbolAddress((void**)&at0, g_att0);
    cudaGetSymbolAddress((void**)&at1, g_att1);
    cudaGetSymbolAddress((void**)&wq0, g_wq0);
    cudaGetSymbolAddress((void**)&wq1, g_wq1);
    cudaGetSymbolAddress((void**)&wp0, g_wp0);
    cudaGetSymbolAddress((void**)&wp1, g_wp1);

    const int SMEM = 81920;
    cudaFuncSetAttribute(gemm_cp<NQKV, false>,
                         cudaFuncAttributeMaxDynamicSharedMemorySize, SMEM);
    cudaFuncSetAttribute(gemm_cp<CC, true>,
                         cudaFuncAttributeMaxDynamicSharedMemorySize, SMEM);
    cudaFuncSetAttribute(attn_kernel,
                         cudaFuncAttributeMaxDynamicSharedMemorySize, ATTN_SMEM);

    // 0) weight prep + activation gather/split
    prep_w<<<768, 256>>>(W_qkv, W_proj);
    split_x<<<16384, 256>>>(x);

    // 1) QKV GEMM (HMMA, cp.async): [65536,256] @ [256,768]
    gemm_cp<NQKV, false><<<dim3(NQKV / 128, MTOK / 128), 256, SMEM>>>(
        a0, a1, wq0, wq1, b_qkv, qkv);

    // 2) per (window, head) Linformer attention v2
    attn_kernel<<<BWIN * NHD, 256, ATTN_SMEM>>>(E_k, E_v, k_bank, v_bank);

    // 3) proj GEMM + window-reverse scatter: [65536,256] @ [256,256]
    gemm_cp<CC, true><<<dim3(CC / 128, MTOK / 128), 256, SMEM>>>(
        at0, at1, wp0, wp1, b_proj, out);
}